// round 1
// baseline (speedup 1.0000x reference)
#include <cuda_runtime.h>
#include <cstdint>

#define N_ROWS  16384
#define DIM     256
#define NCODES  8192
#define QELEMS  (N_ROWS * DIM)

#define BM 32
#define BN 64
#define BK 32

// -------- device scratch (no allocations allowed) --------
__device__ __align__(16) float  g_embT[NCODES * DIM];  // embed transposed: [code][dim]
__device__ float  g_enorm[NCODES];
__device__ int    g_ind[N_ROWS];
__device__ double g_diff_acc;

// -------- zero the accumulator (must run inside the graph for replay determinism) --------
__global__ void vq_zero_kernel() {
    if (threadIdx.x == 0) g_diff_acc = 0.0;
}

// -------- ||e_j||^2 for each code --------
__global__ void vq_enorm_kernel(const float* __restrict__ embed) {
    int j = blockIdx.x * blockDim.x + threadIdx.x;   // code index, coalesced over j
    float s = 0.f;
    #pragma unroll 8
    for (int d = 0; d < DIM; ++d) {
        float v = embed[d * NCODES + j];
        s = fmaf(v, v, s);
    }
    g_enorm[j] = s;
}

// -------- transpose embed [256,8192] -> embT [8192,256] for coalesced gather --------
__global__ void vq_transpose_kernel(const float* __restrict__ embed) {
    __shared__ float tile[32][33];
    int j0 = blockIdx.x * 32;       // code tile
    int d0 = blockIdx.y * 32;       // dim tile
    int tx = threadIdx.x, ty = threadIdx.y;   // blockDim (32,8)
    #pragma unroll
    for (int r = 0; r < 32; r += 8)
        tile[ty + r][tx] = embed[(d0 + ty + r) * NCODES + (j0 + tx)];
    __syncthreads();
    #pragma unroll
    for (int r = 0; r < 32; r += 8)
        g_embT[(j0 + ty + r) * DIM + (d0 + tx)] = tile[tx][ty + r];
}

// -------- fused fp32 GEMM (scores) + per-row argmin --------
// score[n][j] = ||e_j||^2 - 2 * dot(x_n, e_j);  ||x_n||^2 omitted (row-constant).
// Block: 256 threads, tile BM=32 rows x BN=64 codes, K streamed in BK=32 chunks
// with register->smem double buffering. Thread micro-tile: 2 rows x 4 cols.
__global__ void __launch_bounds__(256)
vq_gemm_argmin_kernel(const float* __restrict__ x, const float* __restrict__ embed) {
    __shared__ __align__(16) float As[BM * DIM];        // 32 KB: full-K row tile
    __shared__ __align__(16) float Bs[2 * BK * BN];     // 16 KB: double-buffered code tile

    const int tid = threadIdx.x;
    const int tx = tid & 15;        // 16 col-groups of 4
    const int ty = tid >> 4;        // 16 row-groups of 2
    const int r0 = blockIdx.x * BM;

    // Load A tile (BM x DIM), coalesced float4, conflict-free stores.
    #pragma unroll
    for (int p = 0; p < 8; ++p) {
        int f   = p * 256 + tid;          // float4 index within tile
        int row = f >> 6;                 // DIM/4 = 64 float4 per row
        int c4  = f & 63;
        float4 v = *(const float4*)(x + (size_t)(r0 + row) * DIM + c4 * 4);
        *(float4*)(As + row * DIM + c4 * 4) = v;
    }
    __syncthreads();

    float best[2];
    int   bidx[2];
    #pragma unroll
    for (int i = 0; i < 2; ++i) { best[i] = 3.4e38f; bidx[i] = 0; }

    int buf = 0;
    for (int nc = 0; nc < NCODES; nc += BN) {
        float acc[2][4];
        #pragma unroll
        for (int i = 0; i < 2; ++i)
            #pragma unroll
            for (int j = 0; j < 4; ++j) acc[i][j] = 0.f;

        // Preload K-chunk 0 of this code tile into registers.
        // Mapping: f -> (k = f>>4, j4 = f&15); global read coalesced over j4.
        float4 rb0, rb1;
        {
            int k0 = tid >> 4,          j40 = tid & 15;
            int k1 = (tid + 256) >> 4,  j41 = (tid + 256) & 15;
            rb0 = *(const float4*)(embed + (size_t)k0 * NCODES + nc + j40 * 4);
            rb1 = *(const float4*)(embed + (size_t)k1 * NCODES + nc + j41 * 4);
        }

        #pragma unroll 1
        for (int kc = 0; kc < DIM; kc += BK) {
            // Stage current chunk into smem buffer `buf`.
            {
                int k0 = tid >> 4,          j40 = tid & 15;
                int k1 = (tid + 256) >> 4,  j41 = (tid + 256) & 15;
                *(float4*)(Bs + buf * BK * BN + k0 * BN + j40 * 4) = rb0;
                *(float4*)(Bs + buf * BK * BN + k1 * BN + j41 * 4) = rb1;
            }
            __syncthreads();

            // Prefetch next chunk into registers while computing.
            if (kc + BK < DIM) {
                int k0 = tid >> 4,          j40 = tid & 15;
                int k1 = (tid + 256) >> 4,  j41 = (tid + 256) & 15;
                rb0 = *(const float4*)(embed + (size_t)(kc + BK + k0) * NCODES + nc + j40 * 4);
                rb1 = *(const float4*)(embed + (size_t)(kc + BK + k1) * NCODES + nc + j41 * 4);
            }

            const float* Asp = As + kc;
            const float* Bsp = Bs + buf * BK * BN;
            #pragma unroll
            for (int kk = 0; kk < BK; kk += 4) {
                float a_[2][4], b_[4][4];
                #pragma unroll
                for (int i = 0; i < 2; ++i) {
                    float4 av = *(const float4*)(Asp + (ty * 2 + i) * DIM + kk);
                    a_[i][0] = av.x; a_[i][1] = av.y; a_[i][2] = av.z; a_[i][3] = av.w;
                }
                #pragma unroll
                for (int k2 = 0; k2 < 4; ++k2) {
                    float4 bv = *(const float4*)(Bsp + (kk + k2) * BN + tx * 4);
                    b_[k2][0] = bv.x; b_[k2][1] = bv.y; b_[k2][2] = bv.z; b_[k2][3] = bv.w;
                }
                #pragma unroll
                for (int i = 0; i < 2; ++i)
                    #pragma unroll
                    for (int j = 0; j < 4; ++j) {
                        acc[i][j] = fmaf(a_[i][0], b_[0][j], acc[i][j]);
                        acc[i][j] = fmaf(a_[i][1], b_[1][j], acc[i][j]);
                        acc[i][j] = fmaf(a_[i][2], b_[2][j], acc[i][j]);
                        acc[i][j] = fmaf(a_[i][3], b_[3][j], acc[i][j]);
                    }
            }
            __syncthreads();
            buf ^= 1;
        }

        // Epilogue: scores + running argmin (ascending code order -> strict '<'
        // preserves first-min semantics like jnp.argmin).
        #pragma unroll
        for (int j = 0; j < 4; ++j) {
            int code = nc + tx * 4 + j;
            float en = g_enorm[code];
            #pragma unroll
            for (int i = 0; i < 2; ++i) {
                float s = en - 2.f * acc[i][j];
                if (s < best[i]) { best[i] = s; bidx[i] = code; }
            }
        }
    }

    // Cross-thread (tx) reduction; reuse Bs as scratch (done with tiles).
    __syncthreads();
    float* redS = Bs;                         // BM*16 floats = 2 KB
    int*   redI = (int*)(Bs + BM * 16);       // BM*16 ints  = 2 KB (fits in 16 KB)
    #pragma unroll
    for (int i = 0; i < 2; ++i) {
        int row = ty * 2 + i;
        redS[row * 16 + tx] = best[i];
        redI[row * 16 + tx] = bidx[i];
    }
    __syncthreads();
    if (tid < BM) {
        float b  = redS[tid * 16];
        int   bi = redI[tid * 16];
        #pragma unroll
        for (int t = 1; t < 16; ++t) {
            float s  = redS[tid * 16 + t];
            int   si = redI[tid * 16 + t];
            if (s < b || (s == b && si < bi)) { b = s; bi = si; }
        }
        g_ind[r0 + tid] = bi;
    }
}

// -------- gather codebook rows, write quantize + ind, accumulate diff --------
__global__ void vq_gather_kernel(const float* __restrict__ x,
                                 float* __restrict__ outQ,
                                 float* __restrict__ outInd) {
    const int warp = threadIdx.x >> 5;
    const int lane = threadIdx.x & 31;
    const int row  = blockIdx.x * 8 + warp;

    const int j = g_ind[row];
    const float* e  = g_embT + (size_t)j * DIM;
    const float* xr = x + (size_t)row * DIM;
    float*       qo = outQ + (size_t)row * DIM;

    float s = 0.f;
    #pragma unroll
    for (int p = 0; p < 2; ++p) {
        float4 ev = *(const float4*)(e  + p * 128 + lane * 4);
        float4 xv = *(const float4*)(xr + p * 128 + lane * 4);
        float dx = ev.x - xv.x, dy = ev.y - xv.y, dz = ev.z - xv.z, dw = ev.w - xv.w;
        s += dx * dx + dy * dy + dz * dz + dw * dw;
        *(float4*)(qo + p * 128 + lane * 4) = ev;
    }
    #pragma unroll
    for (int o = 16; o > 0; o >>= 1) s += __shfl_xor_sync(0xffffffffu, s, o);

    __shared__ double bsum[8];
    if (lane == 0) {
        bsum[warp] = (double)s;
        outInd[row] = (float)j;
    }
    __syncthreads();
    if (threadIdx.x == 0) {
        double t = 0.0;
        #pragma unroll
        for (int w = 0; w < 8; ++w) t += bsum[w];
        atomicAdd(&g_diff_acc, t);   // 2048 atomics total -> negligible
    }
}

__global__ void vq_finalize_kernel(float* __restrict__ outDiff) {
    if (threadIdx.x == 0)
        outDiff[0] = (float)(g_diff_acc * 1.25 / (double)QELEMS);
}

// -------- launch --------
extern "C" void kernel_launch(void* const* d_in, const int* in_sizes, int n_in,
                              void* d_out, int out_size) {
    const float* x     = (const float*)d_in[0];   // [16,32,32,256] -> [16384,256]
    const float* embed = (const float*)d_in[1];   // [256,8192]
    float* out     = (float*)d_out;
    float* outQ    = out;                 // 4,194,304 floats
    float* outDiff = out + QELEMS;        // 1 float
    float* outInd  = out + QELEMS + 1;    // 16,384 floats (indices as float)

    vq_zero_kernel<<<1, 32>>>();
    vq_enorm_kernel<<<NCODES / 256, 256>>>(embed);
    vq_transpose_kernel<<<dim3(NCODES / 32, DIM / 32), dim3(32, 8)>>>(embed);
    vq_gemm_argmin_kernel<<<N_ROWS / BM, 256>>>(x, embed);
    vq_gather_kernel<<<N_ROWS / 8, 256>>>(x, outQ, outInd);
    vq_finalize_kernel<<<1, 32>>>(outDiff);
}

// round 3
// speedup vs baseline: 3.6272x; 3.6272x over previous
#include <cuda_runtime.h>
#include <cuda_bf16.h>
#include <cstdint>

#define N_ROWS  16384
#define DIM     256
#define NCODES  8192
#define QELEMS  (N_ROWS * DIM)

#define MTILE   128
#define NT      128
#define KC      32
#define NTILES  (NCODES / NT)          // 64
#define NCH     (NTILES * (DIM / KC))  // 512 chunks

#define AP_B    528                    // A row pitch bytes (264 bf16)
#define BP_B    80                     // B row pitch bytes (40 bf16)
#define A_HI_OFF 0
#define A_LO_OFF (128 * AP_B)          // 67584
#define B_OFF    (2 * 128 * AP_B)      // 135168
#define BSEG     (128 * BP_B)          // 10240
#define SMEM_BYTES (B_OFF + 4 * BSEG)  // 176128

// -------- device scratch --------
__device__ __align__(16) float          g_embT[NCODES * DIM];
__device__ __align__(16) __nv_bfloat16  g_embT_hi[NCODES * DIM];
__device__ __align__(16) __nv_bfloat16  g_embT_lo[NCODES * DIM];
__device__ float  g_enorm[NCODES];
__device__ int    g_ind[N_ROWS];
__device__ float  g_b1[N_ROWS];
__device__ float  g_b2[N_ROWS];
__device__ int    g_i2[N_ROWS];
__device__ double g_diff_acc;

// -------- portable PTX helpers (no sm_103a-gated instructions!) --------
__device__ __forceinline__ uint32_t smem_u32(const void* p) {
    uint32_t a;
    asm("{ .reg .u64 t; cvta.to.shared.u64 t, %1; cvt.u32.u64 %0, t; }" : "=r"(a) : "l"(p));
    return a;
}
#define CP16(dst, src) \
    asm volatile("cp.async.cg.shared.global [%0], [%1], 16;" :: "r"(dst), "l"(src))
#define CP_COMMIT() asm volatile("cp.async.commit_group;" ::: "memory")
#define CP_WAIT0()  asm volatile("cp.async.wait_group 0;" ::: "memory")
#define CP_WAIT1()  asm volatile("cp.async.wait_group 1;" ::: "memory")

#define LDSM4(R0, R1, R2, R3, ADDR) \
    asm volatile("ldmatrix.sync.aligned.m8n8.x4.shared.b16 {%0,%1,%2,%3}, [%4];" \
                 : "=r"(R0), "=r"(R1), "=r"(R2), "=r"(R3) : "r"(ADDR))

#define MMA16816(C, A, B0, B1) \
    asm volatile("mma.sync.aligned.m16n8k16.row.col.f32.bf16.bf16.f32 " \
                 "{%0,%1,%2,%3},{%4,%5,%6,%7},{%8,%9},{%0,%1,%2,%3};" \
                 : "+f"((C)[0]), "+f"((C)[1]), "+f"((C)[2]), "+f"((C)[3]) \
                 : "r"((A)[0]), "r"((A)[1]), "r"((A)[2]), "r"((A)[3]), "r"(B0), "r"(B1))

// ======================= prep kernels =======================
__global__ void vq_zero_kernel() { if (threadIdx.x == 0) g_diff_acc = 0.0; }

__global__ void vq_enorm_kernel(const float* __restrict__ embed) {
    int j = blockIdx.x * blockDim.x + threadIdx.x;
    float s = 0.f;
    #pragma unroll 8
    for (int d = 0; d < DIM; ++d) { float v = embed[d * NCODES + j]; s = fmaf(v, v, s); }
    g_enorm[j] = s;
}

__global__ void vq_transpose_kernel(const float* __restrict__ embed) {
    __shared__ float tile[32][33];
    int j0 = blockIdx.x * 32, d0 = blockIdx.y * 32;
    int tx = threadIdx.x, ty = threadIdx.y;   // (32,8)
    #pragma unroll
    for (int r = 0; r < 32; r += 8)
        tile[ty + r][tx] = embed[(d0 + ty + r) * NCODES + (j0 + tx)];
    __syncthreads();
    #pragma unroll
    for (int r = 0; r < 32; r += 8) {
        float v = tile[tx][ty + r];
        size_t o = (size_t)(j0 + ty + r) * DIM + (d0 + tx);
        g_embT[o] = v;
        __nv_bfloat16 h = __float2bfloat16(v);
        g_embT_hi[o] = h;
        g_embT_lo[o] = __float2bfloat16(v - __bfloat162float(h));
    }
}

// ======================= fused HMMA GEMM + argmin =======================
extern __shared__ __align__(128) char sm_dyn[];

__device__ __forceinline__ void load_b_chunk(int tid, int c, int buf) {
    const int nt = c >> 3, kc = c & 7;
    #pragma unroll
    for (int j = 0; j < 4; ++j) {
        int job = tid + j * 256;
        int hf  = job >> 9;              // 0 = hi, 1 = lo
        int r   = (job >> 2) & 127;
        int q   = job & 3;
        const __nv_bfloat16* src = (hf ? g_embT_lo : g_embT_hi)
            + (size_t)(nt * NT + r) * DIM + kc * KC + q * 8;
        uint32_t dst = smem_u32(sm_dyn + B_OFF + (buf * 2 + hf) * BSEG + r * BP_B + q * 16);
        CP16(dst, src);
    }
}

__global__ void __launch_bounds__(256, 1)
vq_mma_kernel(const float* __restrict__ x) {
    const int tid = threadIdx.x;
    const int wid = tid >> 5, lane = tid & 31;
    const int wm = wid & 1, wn = wid >> 1;    // warp grid 2 (M) x 4 (N)
    const int r0 = blockIdx.x * MTILE;

    // ---- A: load x fp32 [128,256], split bf16 hi/lo into padded smem ----
    #pragma unroll 4
    for (int it = 0; it < 32; ++it) {
        int f   = tid + it * 256;             // 8192 float4 total
        int row = f >> 6, c4 = f & 63;
        float4 v = *(const float4*)(x + (size_t)(r0 + row) * DIM + c4 * 4);
        float fv[4] = {v.x, v.y, v.z, v.w};
        unsigned short hh[4], ll[4];
        #pragma unroll
        for (int j = 0; j < 4; ++j) {
            __nv_bfloat16 h = __float2bfloat16(fv[j]);
            __nv_bfloat16 l = __float2bfloat16(fv[j] - __bfloat162float(h));
            hh[j] = __bfloat16_as_ushort(h);
            ll[j] = __bfloat16_as_ushort(l);
        }
        uint2 uh = make_uint2(hh[0] | ((uint32_t)hh[1] << 16), hh[2] | ((uint32_t)hh[3] << 16));
        uint2 ul = make_uint2(ll[0] | ((uint32_t)ll[1] << 16), ll[2] | ((uint32_t)ll[3] << 16));
        *(uint2*)(sm_dyn + A_HI_OFF + row * AP_B + c4 * 8) = uh;
        *(uint2*)(sm_dyn + A_LO_OFF + row * AP_B + c4 * 8) = ul;
    }
    __syncthreads();

    float acc[4][4][4];
    #pragma unroll
    for (int a = 0; a < 4; ++a)
        #pragma unroll
        for (int b = 0; b < 4; ++b)
            #pragma unroll
            for (int k = 0; k < 4; ++k) acc[a][b][k] = 0.f;

    float rb1[8], rb2[8]; int ri1[8], ri2[8];
    #pragma unroll
    for (int s = 0; s < 8; ++s) { rb1[s] = 3.4e38f; rb2[s] = 3.4e38f; ri1[s] = 0; ri2[s] = 0; }

    // ldmatrix lane addressing (shared by A and B tiles)
    const int r_in  = lane & 7;
    const int quad  = lane >> 3;
    const int lrow  = (quad & 1) * 8 + r_in;
    const int lkoff = (quad >> 1) * 8;

    load_b_chunk(tid, 0, 0);
    CP_COMMIT();

    for (int c = 0; c < NCH; ++c) {
        const int buf = c & 1;
        if (c + 1 < NCH) { load_b_chunk(tid, c + 1, buf ^ 1); CP_COMMIT(); CP_WAIT1(); }
        else             { CP_WAIT0(); }
        __syncthreads();

        const char* bh_base = sm_dyn + B_OFF + (buf * 2 + 0) * BSEG;
        const char* bl_base = sm_dyn + B_OFF + (buf * 2 + 1) * BSEG;
        const int kc = c & 7;

        #pragma unroll
        for (int ks = 0; ks < 2; ++ks) {
            const int kg = kc * 32 + ks * 16;    // K position in A tile
            uint32_t ah[4][4], al[4][4];
            #pragma unroll
            for (int mf = 0; mf < 4; ++mf) {
                uint32_t off = (uint32_t)(wm * 64 + mf * 16 + lrow) * AP_B + (kg + lkoff) * 2;
                uint32_t a_h = smem_u32(sm_dyn + A_HI_OFF + off);
                uint32_t a_l = smem_u32(sm_dyn + A_LO_OFF + off);
                LDSM4(ah[mf][0], ah[mf][1], ah[mf][2], ah[mf][3], a_h);
                LDSM4(al[mf][0], al[mf][1], al[mf][2], al[mf][3], a_l);
            }
            uint32_t bh[4][2], bl[4][2];
            #pragma unroll
            for (int g = 0; g < 2; ++g) {
                uint32_t boff = (uint32_t)(wn * 32 + g * 16 + lrow) * BP_B + (ks * 16 + lkoff) * 2;
                uint32_t t0, t1, t2, t3;
                LDSM4(t0, t1, t2, t3, smem_u32(bh_base + boff));
                bh[g * 2 + 0][0] = t0; bh[g * 2 + 0][1] = t2;
                bh[g * 2 + 1][0] = t1; bh[g * 2 + 1][1] = t3;
                LDSM4(t0, t1, t2, t3, smem_u32(bl_base + boff));
                bl[g * 2 + 0][0] = t0; bl[g * 2 + 0][1] = t2;
                bl[g * 2 + 1][0] = t1; bl[g * 2 + 1][1] = t3;
            }
            #pragma unroll
            for (int mf = 0; mf < 4; ++mf)
                #pragma unroll
                for (int nf = 0; nf < 4; ++nf) {
                    MMA16816(acc[mf][nf], ah[mf], bh[nf][0], bh[nf][1]);
                    MMA16816(acc[mf][nf], ah[mf], bl[nf][0], bl[nf][1]);
                    MMA16816(acc[mf][nf], al[mf], bh[nf][0], bh[nf][1]);
                }
        }

        if ((c & 7) == 7) {     // end of an N-tile: fold scores into argmin trackers
            const int nt = c >> 3;
            const int cbase = nt * NT + wn * 32 + (lane & 3) * 2;
            #pragma unroll
            for (int nf = 0; nf < 4; ++nf) {
                float2 en2 = __ldg((const float2*)(g_enorm + cbase + nf * 8));
                #pragma unroll
                for (int b = 0; b < 2; ++b) {
                    const float en  = b ? en2.y : en2.x;
                    const int  code = cbase + nf * 8 + b;
                    #pragma unroll
                    for (int mf = 0; mf < 4; ++mf)
                        #pragma unroll
                        for (int hf = 0; hf < 2; ++hf) {
                            float sc = fmaf(-2.f, acc[mf][nf][hf * 2 + b], en);
                            int s = mf * 2 + hf;
                            if (sc < rb2[s]) {
                                if (sc < rb1[s]) { rb2[s] = rb1[s]; ri2[s] = ri1[s];
                                                   rb1[s] = sc;     ri1[s] = code; }
                                else             { rb2[s] = sc;     ri2[s] = code; }
                            }
                        }
                }
            }
            #pragma unroll
            for (int a = 0; a < 4; ++a)
                #pragma unroll
                for (int b = 0; b < 4; ++b)
                    #pragma unroll
                    for (int k = 0; k < 4; ++k) acc[a][b][k] = 0.f;
        }
        __syncthreads();
    }

    // ---- reduce best-2 across the 4 lanes sharing each row (quad shfl) ----
    #pragma unroll
    for (int s = 0; s < 8; ++s) {
        #pragma unroll
        for (int off = 1; off <= 2; off <<= 1) {
            float ob1 = __shfl_xor_sync(0xffffffffu, rb1[s], off);
            float ob2 = __shfl_xor_sync(0xffffffffu, rb2[s], off);
            int   oi1 = __shfl_xor_sync(0xffffffffu, ri1[s], off);
            int   oi2 = __shfl_xor_sync(0xffffffffu, ri2[s], off);
            if (ob1 < rb1[s] || (ob1 == rb1[s] && oi1 < ri1[s])) {
                float tb = rb1[s]; int ti = ri1[s];
                rb1[s] = ob1; ri1[s] = oi1; ob1 = tb; oi1 = ti;
            }
            if (ob1 < rb2[s]) { rb2[s] = ob1; ri2[s] = oi1; }
            if (ob2 < rb2[s]) { rb2[s] = ob2; ri2[s] = oi2; }
        }
    }
    __syncthreads();                     // done with B smem -> reuse as scratch
    if ((lane & 3) == 0) {
        #pragma unroll
        for (int s = 0; s < 8; ++s) {
            int mf = s >> 1, hf = s & 1;
            int row = wm * 64 + mf * 16 + (lane >> 2) + hf * 8;
            float4 v;
            v.x = rb1[s]; v.y = rb2[s];
            v.z = __int_as_float(ri1[s]); v.w = __int_as_float(ri2[s]);
            *(float4*)(sm_dyn + B_OFF + (wn * 128 + row) * 16) = v;
        }
    }
    __syncthreads();
    if (tid < 128) {
        float4 v = *(float4*)(sm_dyn + B_OFF + tid * 16);
        float b1 = v.x, b2 = v.y;
        int i1 = __float_as_int(v.z), i2 = __float_as_int(v.w);
        #pragma unroll
        for (int w = 1; w < 4; ++w) {
            float4 u = *(float4*)(sm_dyn + B_OFF + (w * 128 + tid) * 16);
            float ob1 = u.x, ob2 = u.y;
            int oi1 = __float_as_int(u.z), oi2 = __float_as_int(u.w);
            if (ob1 < b1 || (ob1 == b1 && oi1 < i1)) {
                float tb = b1; int ti = i1;
                b1 = ob1; i1 = oi1; ob1 = tb; oi1 = ti;
            }
            if (ob1 < b2) { b2 = ob1; i2 = oi1; }
            if (ob2 < b2) { b2 = ob2; i2 = oi2; }
        }
        int row = r0 + tid;
        g_ind[row] = i1; g_b1[row] = b1; g_b2[row] = b2; g_i2[row] = i2;
    }
}

// ======================= exact rescue for near-ties =======================
__global__ void vq_fixup_kernel(const float* __restrict__ x) {
    const int warp = threadIdx.x >> 5, lane = threadIdx.x & 31;
    const int row = blockIdx.x * 8 + warp;
    float b1 = g_b1[row], b2 = g_b2[row];
    if (b2 - b1 >= 0.01f) return;
    int i1 = g_ind[row], i2 = g_i2[row];
    const float* xr = x + (size_t)row * DIM;
    const float* e1 = g_embT + (size_t)i1 * DIM;
    const float* e2 = g_embT + (size_t)i2 * DIM;
    float d1 = 0.f, d2 = 0.f;
    #pragma unroll
    for (int t = lane; t < DIM; t += 32) {
        float xv = xr[t];
        d1 = fmaf(xv, e1[t], d1);
        d2 = fmaf(xv, e2[t], d2);
    }
    #pragma unroll
    for (int o = 16; o > 0; o >>= 1) {
        d1 += __shfl_xor_sync(0xffffffffu, d1, o);
        d2 += __shfl_xor_sync(0xffffffffu, d2, o);
    }
    if (lane == 0) {
        float s1 = g_enorm[i1] - 2.f * d1;
        float s2 = g_enorm[i2] - 2.f * d2;
        g_ind[row] = (s2 < s1 || (s2 == s1 && i2 < i1)) ? i2 : i1;
    }
}

// ======================= gather + loss =======================
__global__ void vq_gather_kernel(const float* __restrict__ x,
                                 float* __restrict__ outQ,
                                 float* __restrict__ outInd) {
    const int warp = threadIdx.x >> 5, lane = threadIdx.x & 31;
    const int row  = blockIdx.x * 8 + warp;
    const int j = g_ind[row];
    const float* e  = g_embT + (size_t)j * DIM;
    const float* xr = x + (size_t)row * DIM;
    float*       qo = outQ + (size_t)row * DIM;
    float s = 0.f;
    #pragma unroll
    for (int p = 0; p < 2; ++p) {
        float4 ev = *(const float4*)(e  + p * 128 + lane * 4);
        float4 xv = *(const float4*)(xr + p * 128 + lane * 4);
        float dx = ev.x - xv.x, dy = ev.y - xv.y, dz = ev.z - xv.z, dw = ev.w - xv.w;
        s += dx * dx + dy * dy + dz * dz + dw * dw;
        *(float4*)(qo + p * 128 + lane * 4) = ev;
    }
    #pragma unroll
    for (int o = 16; o > 0; o >>= 1) s += __shfl_xor_sync(0xffffffffu, s, o);
    __shared__ double bsum[8];
    if (lane == 0) { bsum[warp] = (double)s; outInd[row] = (float)j; }
    __syncthreads();
    if (threadIdx.x == 0) {
        double t = 0.0;
        #pragma unroll
        for (int w = 0; w < 8; ++w) t += bsum[w];
        atomicAdd(&g_diff_acc, t);
    }
}

__global__ void vq_finalize_kernel(float* __restrict__ outDiff) {
    if (threadIdx.x == 0)
        outDiff[0] = (float)(g_diff_acc * 1.25 / (double)QELEMS);
}

// ======================= launch =======================
extern "C" void kernel_launch(void* const* d_in, const int* in_sizes, int n_in,
                              void* d_out, int out_size) {
    const float* x     = (const float*)d_in[0];
    const float* embed = (const float*)d_in[1];
    float* out     = (float*)d_out;
    float* outQ    = out;
    float* outDiff = out + QELEMS;
    float* outInd  = out + QELEMS + 1;

    cudaFuncSetAttribute(vq_mma_kernel, cudaFuncAttributeMaxDynamicSharedMemorySize, SMEM_BYTES);

    vq_zero_kernel<<<1, 32>>>();
    vq_enorm_kernel<<<NCODES / 256, 256>>>(embed);
    vq_transpose_kernel<<<dim3(NCODES / 32, DIM / 32), dim3(32, 8)>>>(embed);
    vq_mma_kernel<<<N_ROWS / MTILE, 256, SMEM_BYTES>>>(x);
    vq_fixup_kernel<<<N_ROWS / 8, 256>>>(x);
    vq_gather_kernel<<<N_ROWS / 8, 256>>>(x, outQ, outInd);
    vq_finalize_kernel<<<1, 32>>>(outDiff);
}

// round 4
// speedup vs baseline: 3.9387x; 1.0859x over previous
#include <cuda_runtime.h>
#include <cuda_bf16.h>
#include <cstdint>

#define N_ROWS  16384
#define DIM     256
#define NCODES  8192
#define QELEMS  (N_ROWS * DIM)

#define MTILE   128
#define NT      128
#define KC      64
#define NTILES  (NCODES / NT)          // 64
#define NCH     (NTILES * (DIM / KC))  // 256 chunks

#define AP_B    528                    // A row pitch bytes
#define BP_B    144                    // B row pitch bytes (64 bf16 + pad)
#define A_HI_OFF 0
#define A_LO_OFF (128 * AP_B)          // 67584
#define B_OFF    (2 * 128 * AP_B)      // 135168
#define BSEG     (128 * BP_B)          // 18432
#define SMEM_BYTES (B_OFF + 4 * BSEG)  // 208896

// -------- device scratch --------
__device__ __align__(16) float          g_embT[NCODES * DIM];
__device__ __align__(16) __nv_bfloat16  g_embT_hi[NCODES * DIM];
__device__ __align__(16) __nv_bfloat16  g_embT_lo[NCODES * DIM];
__device__ float  g_enorm[NCODES];
__device__ int    g_ind[N_ROWS];
__device__ float  g_b1[N_ROWS];
__device__ float  g_b2[N_ROWS];
__device__ int    g_i2[N_ROWS];
__device__ double g_diff_acc;

// -------- portable PTX helpers --------
__device__ __forceinline__ uint32_t smem_u32(const void* p) {
    uint32_t a;
    asm("{ .reg .u64 t; cvta.to.shared.u64 t, %1; cvt.u32.u64 %0, t; }" : "=r"(a) : "l"(p));
    return a;
}
#define CP16(dst, src) \
    asm volatile("cp.async.cg.shared.global [%0], [%1], 16;" :: "r"(dst), "l"(src))
#define CP_COMMIT() asm volatile("cp.async.commit_group;" ::: "memory")
#define CP_WAIT0()  asm volatile("cp.async.wait_group 0;" ::: "memory")
#define CP_WAIT1()  asm volatile("cp.async.wait_group 1;" ::: "memory")

#define LDSM4(R0, R1, R2, R3, ADDR) \
    asm volatile("ldmatrix.sync.aligned.m8n8.x4.shared.b16 {%0,%1,%2,%3}, [%4];" \
                 : "=r"(R0), "=r"(R1), "=r"(R2), "=r"(R3) : "r"(ADDR))

#define MMA16816(C, A, B0, B1) \
    asm volatile("mma.sync.aligned.m16n8k16.row.col.f32.bf16.bf16.f32 " \
                 "{%0,%1,%2,%3},{%4,%5,%6,%7},{%8,%9},{%0,%1,%2,%3};" \
                 : "+f"((C)[0]), "+f"((C)[1]), "+f"((C)[2]), "+f"((C)[3]) \
                 : "r"((A)[0]), "r"((A)[1]), "r"((A)[2]), "r"((A)[3]), "r"(B0), "r"(B1))

// ======================= prep kernels =======================
__global__ void vq_zero_kernel() { if (threadIdx.x == 0) g_diff_acc = 0.0; }

__global__ void vq_enorm_kernel(const float* __restrict__ embed) {
    int j = blockIdx.x * blockDim.x + threadIdx.x;
    float s = 0.f;
    #pragma unroll 8
    for (int d = 0; d < DIM; ++d) { float v = embed[d * NCODES + j]; s = fmaf(v, v, s); }
    g_enorm[j] = s;
}

__global__ void vq_transpose_kernel(const float* __restrict__ embed) {
    __shared__ float tile[32][33];
    int j0 = blockIdx.x * 32, d0 = blockIdx.y * 32;
    int tx = threadIdx.x, ty = threadIdx.y;   // (32,8)
    #pragma unroll
    for (int r = 0; r < 32; r += 8)
        tile[ty + r][tx] = embed[(d0 + ty + r) * NCODES + (j0 + tx)];
    __syncthreads();
    #pragma unroll
    for (int r = 0; r < 32; r += 8) {
        float v = tile[tx][ty + r];
        size_t o = (size_t)(j0 + ty + r) * DIM + (d0 + tx);
        g_embT[o] = v;
        __nv_bfloat16 h = __float2bfloat16(v);
        g_embT_hi[o] = h;
        g_embT_lo[o] = __float2bfloat16(v - __bfloat162float(h));
    }
}

// ======================= fused HMMA GEMM + argmin =======================
extern __shared__ __align__(128) char sm_dyn[];

__device__ __forceinline__ void load_b_chunk(int tid, int c, int buf) {
    const int nt = c >> 2, kc = c & 3;
    #pragma unroll
    for (int j = 0; j < 4; ++j) {
        int job = tid + j * 512;             // 2048 x 16B copies
        int hf  = job >> 10;                 // 0 = hi, 1 = lo
        int r   = (job >> 3) & 127;
        int q   = job & 7;
        const __nv_bfloat16* src = (hf ? g_embT_lo : g_embT_hi)
            + (size_t)(nt * NT + r) * DIM + kc * KC + q * 8;
        uint32_t dst = smem_u32(sm_dyn + B_OFF + (buf * 2 + hf) * BSEG + r * BP_B + q * 16);
        CP16(dst, src);
    }
}

__global__ void __launch_bounds__(512, 1)
vq_mma_kernel(const float* __restrict__ x) {
    const int tid = threadIdx.x;
    const int wid = tid >> 5, lane = tid & 31;
    const int wm = wid & 3, wn = wid >> 2;    // warp grid 4 (M) x 4 (N)
    const int r0 = blockIdx.x * MTILE;

    // ---- A: load x fp32 [128,256], split bf16 hi/lo into padded smem ----
    #pragma unroll 4
    for (int it = 0; it < 16; ++it) {
        int f   = tid + it * 512;             // 8192 float4 total
        int row = f >> 6, c4 = f & 63;
        float4 v = *(const float4*)(x + (size_t)(r0 + row) * DIM + c4 * 4);
        float fv[4] = {v.x, v.y, v.z, v.w};
        unsigned short hh[4], ll[4];
        #pragma unroll
        for (int j = 0; j < 4; ++j) {
            __nv_bfloat16 h = __float2bfloat16(fv[j]);
            __nv_bfloat16 l = __float2bfloat16(fv[j] - __bfloat162float(h));
            hh[j] = __bfloat16_as_ushort(h);
            ll[j] = __bfloat16_as_ushort(l);
        }
        uint2 uh = make_uint2(hh[0] | ((uint32_t)hh[1] << 16), hh[2] | ((uint32_t)hh[3] << 16));
        uint2 ul = make_uint2(ll[0] | ((uint32_t)ll[1] << 16), ll[2] | ((uint32_t)ll[3] << 16));
        *(uint2*)(sm_dyn + A_HI_OFF + row * AP_B + c4 * 8) = uh;
        *(uint2*)(sm_dyn + A_LO_OFF + row * AP_B + c4 * 8) = ul;
    }
    __syncthreads();

    float acc[2][4][4];
    #pragma unroll
    for (int a = 0; a < 2; ++a)
        #pragma unroll
        for (int b = 0; b < 4; ++b)
            #pragma unroll
            for (int k = 0; k < 4; ++k) acc[a][b][k] = 0.f;

    float rb1[4], rb2[4]; int ri1[4], ri2[4];
    #pragma unroll
    for (int s = 0; s < 4; ++s) { rb1[s] = 3.4e38f; rb2[s] = 3.4e38f; ri1[s] = 0; ri2[s] = 0; }

    const int r_in  = lane & 7;
    const int quad  = lane >> 3;
    const int lrow  = (quad & 1) * 8 + r_in;
    const int lkoff = (quad >> 1) * 8;

    load_b_chunk(tid, 0, 0);
    CP_COMMIT();

    for (int c = 0; c < NCH; ++c) {
        const int buf = c & 1;
        if (c + 1 < NCH) { load_b_chunk(tid, c + 1, buf ^ 1); CP_COMMIT(); CP_WAIT1(); }
        else             { CP_WAIT0(); }
        __syncthreads();

        const char* bh_base = sm_dyn + B_OFF + (buf * 2 + 0) * BSEG;
        const char* bl_base = sm_dyn + B_OFF + (buf * 2 + 1) * BSEG;
        const int kc = c & 3;

        #pragma unroll
        for (int ks = 0; ks < 4; ++ks) {
            const int kg = kc * KC + ks * 16;    // K position in A tile
            uint32_t ah[2][4], al[2][4];
            #pragma unroll
            for (int mf = 0; mf < 2; ++mf) {
                uint32_t off = (uint32_t)(wm * 32 + mf * 16 + lrow) * AP_B + (kg + lkoff) * 2;
                LDSM4(ah[mf][0], ah[mf][1], ah[mf][2], ah[mf][3], smem_u32(sm_dyn + A_HI_OFF + off));
                LDSM4(al[mf][0], al[mf][1], al[mf][2], al[mf][3], smem_u32(sm_dyn + A_LO_OFF + off));
            }
            uint32_t bh[4][2], bl[4][2];
            #pragma unroll
            for (int g = 0; g < 2; ++g) {
                uint32_t boff = (uint32_t)(wn * 32 + g * 16 + lrow) * BP_B + (ks * 16 + lkoff) * 2;
                uint32_t t0, t1, t2, t3;
                LDSM4(t0, t1, t2, t3, smem_u32(bh_base + boff));
                bh[g * 2 + 0][0] = t0; bh[g * 2 + 0][1] = t2;
                bh[g * 2 + 1][0] = t1; bh[g * 2 + 1][1] = t3;
                LDSM4(t0, t1, t2, t3, smem_u32(bl_base + boff));
                bl[g * 2 + 0][0] = t0; bl[g * 2 + 0][1] = t2;
                bl[g * 2 + 1][0] = t1; bl[g * 2 + 1][1] = t3;
            }
            #pragma unroll
            for (int mf = 0; mf < 2; ++mf)
                #pragma unroll
                for (int nf = 0; nf < 4; ++nf) {
                    MMA16816(acc[mf][nf], ah[mf], bh[nf][0], bh[nf][1]);
                    MMA16816(acc[mf][nf], ah[mf], bl[nf][0], bl[nf][1]);
                    MMA16816(acc[mf][nf], al[mf], bh[nf][0], bh[nf][1]);
                }
        }

        if ((c & 3) == 3) {     // end of an N-tile: fold scores into argmin trackers
            const int nt = c >> 2;
            const int cbase = nt * NT + wn * 32 + (lane & 3) * 2;
            #pragma unroll
            for (int nf = 0; nf < 4; ++nf) {
                float2 en2 = __ldg((const float2*)(g_enorm + cbase + nf * 8));
                #pragma unroll
                for (int b = 0; b < 2; ++b) {
                    const float en  = b ? en2.y : en2.x;
                    const int  code = cbase + nf * 8 + b;
                    #pragma unroll
                    for (int mf = 0; mf < 2; ++mf)
                        #pragma unroll
                        for (int hf = 0; hf < 2; ++hf) {
                            float sc = fmaf(-2.f, acc[mf][nf][hf * 2 + b], en);
                            int s = mf * 2 + hf;
                            if (sc < rb2[s]) {
                                if (sc < rb1[s]) { rb2[s] = rb1[s]; ri2[s] = ri1[s];
                                                   rb1[s] = sc;     ri1[s] = code; }
                                else             { rb2[s] = sc;     ri2[s] = code; }
                            }
                        }
                }
            }
            #pragma unroll
            for (int a = 0; a < 2; ++a)
                #pragma unroll
                for (int b = 0; b < 4; ++b)
                    #pragma unroll
                    for (int k = 0; k < 4; ++k) acc[a][b][k] = 0.f;
        }
        __syncthreads();
    }

    // ---- reduce best-2 across the 4 lanes sharing each row (quad shfl) ----
    #pragma unroll
    for (int s = 0; s < 4; ++s) {
        #pragma unroll
        for (int off = 1; off <= 2; off <<= 1) {
            float ob1 = __shfl_xor_sync(0xffffffffu, rb1[s], off);
            float ob2 = __shfl_xor_sync(0xffffffffu, rb2[s], off);
            int   oi1 = __shfl_xor_sync(0xffffffffu, ri1[s], off);
            int   oi2 = __shfl_xor_sync(0xffffffffu, ri2[s], off);
            if (ob1 < rb1[s] || (ob1 == rb1[s] && oi1 < ri1[s])) {
                float tb = rb1[s]; int ti = ri1[s];
                rb1[s] = ob1; ri1[s] = oi1; ob1 = tb; oi1 = ti;
            }
            if (ob1 < rb2[s]) { rb2[s] = ob1; ri2[s] = oi1; }
            if (ob2 < rb2[s]) { rb2[s] = ob2; ri2[s] = oi2; }
        }
    }
    __syncthreads();                     // done with B smem -> reuse as scratch
    if ((lane & 3) == 0) {
        #pragma unroll
        for (int s = 0; s < 4; ++s) {
            int mf = s >> 1, hf = s & 1;
            int row = wm * 32 + mf * 16 + (lane >> 2) + hf * 8;
            float4 v;
            v.x = rb1[s]; v.y = rb2[s];
            v.z = __int_as_float(ri1[s]); v.w = __int_as_float(ri2[s]);
            *(float4*)(sm_dyn + B_OFF + (wn * 128 + row) * 16) = v;
        }
    }
    __syncthreads();
    if (tid < 128) {
        float4 v = *(float4*)(sm_dyn + B_OFF + tid * 16);
        float b1 = v.x, b2 = v.y;
        int i1 = __float_as_int(v.z), i2 = __float_as_int(v.w);
        #pragma unroll
        for (int w = 1; w < 4; ++w) {
            float4 u = *(float4*)(sm_dyn + B_OFF + (w * 128 + tid) * 16);
            float ob1 = u.x, ob2 = u.y;
            int oi1 = __float_as_int(u.z), oi2 = __float_as_int(u.w);
            if (ob1 < b1 || (ob1 == b1 && oi1 < i1)) {
                float tb = b1; int ti = i1;
                b1 = ob1; i1 = oi1; ob1 = tb; oi1 = ti;
            }
            if (ob1 < b2) { b2 = ob1; i2 = oi1; }
            if (ob2 < b2) { b2 = ob2; i2 = oi2; }
        }
        int row = r0 + tid;
        g_ind[row] = i1; g_b1[row] = b1; g_b2[row] = b2; g_i2[row] = i2;
    }
}

// ======================= exact rescue for near-ties =======================
__global__ void vq_fixup_kernel(const float* __restrict__ x) {
    const int warp = threadIdx.x >> 5, lane = threadIdx.x & 31;
    const int row = blockIdx.x * 8 + warp;
    float b1 = g_b1[row], b2 = g_b2[row];
    if (b2 - b1 >= 0.01f) return;
    int i1 = g_ind[row], i2 = g_i2[row];
    const float* xr = x + (size_t)row * DIM;
    const float* e1 = g_embT + (size_t)i1 * DIM;
    const float* e2 = g_embT + (size_t)i2 * DIM;
    float d1 = 0.f, d2 = 0.f;
    #pragma unroll
    for (int t = lane; t < DIM; t += 32) {
        float xv = xr[t];
        d1 = fmaf(xv, e1[t], d1);
        d2 = fmaf(xv, e2[t], d2);
    }
    #pragma unroll
    for (int o = 16; o > 0; o >>= 1) {
        d1 += __shfl_xor_sync(0xffffffffu, d1, o);
        d2 += __shfl_xor_sync(0xffffffffu, d2, o);
    }
    if (lane == 0) {
        float s1 = g_enorm[i1] - 2.f * d1;
        float s2 = g_enorm[i2] - 2.f * d2;
        g_ind[row] = (s2 < s1 || (s2 == s1 && i2 < i1)) ? i2 : i1;
    }
}

// ======================= gather + loss =======================
__global__ void vq_gather_kernel(const float* __restrict__ x,
                                 float* __restrict__ outQ,
                                 float* __restrict__ outInd) {
    const int warp = threadIdx.x >> 5, lane = threadIdx.x & 31;
    const int row  = blockIdx.x * 8 + warp;
    const int j = g_ind[row];
    const float* e  = g_embT + (size_t)j * DIM;
    const float* xr = x + (size_t)row * DIM;
    float*       qo = outQ + (size_t)row * DIM;
    float s = 0.f;
    #pragma unroll
    for (int p = 0; p < 2; ++p) {
        float4 ev = *(const float4*)(e  + p * 128 + lane * 4);
        float4 xv = *(const float4*)(xr + p * 128 + lane * 4);
        float dx = ev.x - xv.x, dy = ev.y - xv.y, dz = ev.z - xv.z, dw = ev.w - xv.w;
        s += dx * dx + dy * dy + dz * dz + dw * dw;
        *(float4*)(qo + p * 128 + lane * 4) = ev;
    }
    #pragma unroll
    for (int o = 16; o > 0; o >>= 1) s += __shfl_xor_sync(0xffffffffu, s, o);
    __shared__ double bsum[8];
    if (lane == 0) { bsum[warp] = (double)s; outInd[row] = (float)j; }
    __syncthreads();
    if (threadIdx.x == 0) {
        double t = 0.0;
        #pragma unroll
        for (int w = 0; w < 8; ++w) t += bsum[w];
        atomicAdd(&g_diff_acc, t);
    }
}

__global__ void vq_finalize_kernel(float* __restrict__ outDiff) {
    if (threadIdx.x == 0)
        outDiff[0] = (float)(g_diff_acc * 1.25 / (double)QELEMS);
}

// ======================= launch =======================
extern "C" void kernel_launch(void* const* d_in, const int* in_sizes, int n_in,
                              void* d_out, int out_size) {
    const float* x     = (const float*)d_in[0];
    const float* embed = (const float*)d_in[1];
    float* out     = (float*)d_out;
    float* outQ    = out;
    float* outDiff = out + QELEMS;
    float* outInd  = out + QELEMS + 1;

    cudaFuncSetAttribute(vq_mma_kernel, cudaFuncAttributeMaxDynamicSharedMemorySize, SMEM_BYTES);

    vq_zero_kernel<<<1, 32>>>();
    vq_enorm_kernel<<<NCODES / 256, 256>>>(embed);
    vq_transpose_kernel<<<dim3(NCODES / 32, DIM / 32), dim3(32, 8)>>>(embed);
    vq_mma_kernel<<<N_ROWS / MTILE, 512, SMEM_BYTES>>>(x);
    vq_fixup_kernel<<<N_ROWS / 8, 256>>>(x);
    vq_gather_kernel<<<N_ROWS / 8, 256>>>(x, outQ, outInd);
    vq_finalize_kernel<<<1, 32>>>(outDiff);
}

// round 5
// speedup vs baseline: 4.6095x; 1.1703x over previous
#include <cuda_runtime.h>
#include <cuda_bf16.h>
#include <cstdint>

#define N_ROWS  16384
#define DIM     256
#define NCODES  8192
#define QELEMS  (N_ROWS * DIM)

#define MTILE   128
#define NT      128
#define KC      64
#define NTILES  (NCODES / NT)          // 64
#define NCH     (NTILES * (DIM / KC))  // 256 chunks

// SMEM layout: A hi [128x512B swizzled], A lo, then 3 B stages (hi 16K + lo 16K)
#define A_HI_OFF 0
#define A_LO_OFF 65536
#define B_OFF    131072
#define BSTG     32768
#define SMEM_BYTES (B_OFF + 3 * BSTG)  // 229376

// -------- device scratch --------
__device__ __align__(16) float          g_embT[NCODES * DIM];
__device__ __align__(16) __nv_bfloat16  g_embT_hi[NCODES * DIM];
__device__ __align__(16) __nv_bfloat16  g_embT_lo[NCODES * DIM];
__device__ float  g_enorm[NCODES];
__device__ int    g_ind[N_ROWS];
__device__ float  g_b1[N_ROWS];
__device__ float  g_b2[N_ROWS];
__device__ int    g_i2[N_ROWS];
__device__ double g_diff_acc;

// -------- portable PTX helpers --------
__device__ __forceinline__ uint32_t smem_u32(const void* p) {
    uint32_t a;
    asm("{ .reg .u64 t; cvta.to.shared.u64 t, %1; cvt.u32.u64 %0, t; }" : "=r"(a) : "l"(p));
    return a;
}
#define CP16(dst, src) \
    asm volatile("cp.async.cg.shared.global [%0], [%1], 16;" :: "r"(dst), "l"(src))
#define CP_COMMIT() asm volatile("cp.async.commit_group;" ::: "memory")
#define CP_WAIT1()  asm volatile("cp.async.wait_group 1;" ::: "memory")

#define LDSM4(R0, R1, R2, R3, ADDR) \
    asm volatile("ldmatrix.sync.aligned.m8n8.x4.shared.b16 {%0,%1,%2,%3}, [%4];" \
                 : "=r"(R0), "=r"(R1), "=r"(R2), "=r"(R3) : "r"(ADDR))

#define MMA16816(C, A, B0, B1) \
    asm volatile("mma.sync.aligned.m16n8k16.row.col.f32.bf16.bf16.f32 " \
                 "{%0,%1,%2,%3},{%4,%5,%6,%7},{%8,%9},{%0,%1,%2,%3};" \
                 : "+f"((C)[0]), "+f"((C)[1]), "+f"((C)[2]), "+f"((C)[3]) \
                 : "r"((A)[0]), "r"((A)[1]), "r"((A)[2]), "r"((A)[3]), "r"(B0), "r"(B1))

// ======================= prep kernels =======================
__global__ void vq_zero_kernel() { if (threadIdx.x == 0) g_diff_acc = 0.0; }

__global__ void vq_enorm_kernel(const float* __restrict__ embed) {
    int j = blockIdx.x * blockDim.x + threadIdx.x;
    float s = 0.f;
    #pragma unroll 8
    for (int d = 0; d < DIM; ++d) { float v = embed[d * NCODES + j]; s = fmaf(v, v, s); }
    g_enorm[j] = s;
}

__global__ void vq_transpose_kernel(const float* __restrict__ embed) {
    __shared__ float tile[32][33];
    int j0 = blockIdx.x * 32, d0 = blockIdx.y * 32;
    int tx = threadIdx.x, ty = threadIdx.y;   // (32,8)
    #pragma unroll
    for (int r = 0; r < 32; r += 8)
        tile[ty + r][tx] = embed[(d0 + ty + r) * NCODES + (j0 + tx)];
    __syncthreads();
    #pragma unroll
    for (int r = 0; r < 32; r += 8) {
        float v = tile[tx][ty + r];
        size_t o = (size_t)(j0 + ty + r) * DIM + (d0 + tx);
        g_embT[o] = v;
        __nv_bfloat16 h = __float2bfloat16(v);
        g_embT_hi[o] = h;
        g_embT_lo[o] = __float2bfloat16(v - __bfloat162float(h));
    }
}

// ======================= fused HMMA GEMM + argmin =======================
extern __shared__ __align__(1024) char sm_dyn[];

// B chunk: 128 rows x 64 bf16 (hi + lo), rows 128B, 16B-unit XOR swizzle
__device__ __forceinline__ void load_b_chunk(uint32_t sbase, int tid, int c, int stg) {
    const int nt = c >> 2, kc = c & 3;
    #pragma unroll
    for (int j = 0; j < 4; ++j) {
        int u  = tid + j * 512;            // 0..2047
        int hf = u >> 10;                  // 0 = hi, 1 = lo
        int r  = (u >> 3) & 127;
        int q  = u & 7;
        const __nv_bfloat16* src = (hf ? g_embT_lo : g_embT_hi)
            + (size_t)(nt * NT + r) * DIM + kc * KC + q * 8;
        uint32_t dst = sbase + B_OFF + stg * BSTG + hf * 16384
                     + (r << 7) + ((q ^ (r & 7)) << 4);
        CP16(dst, src);
    }
}

__global__ void __launch_bounds__(512, 1)
vq_mma_kernel(const float* __restrict__ x) {
    const int tid = threadIdx.x;
    const int wid = tid >> 5, lane = tid & 31;
    const int wm = wid & 3, wn = wid >> 2;    // warp grid 4 (M) x 4 (N)
    const int r0 = blockIdx.x * MTILE;
    const uint32_t sbase = smem_u32(sm_dyn);

    // ---- A: load x fp32 [128,256], split bf16 hi/lo, swizzled tight rows ----
    #pragma unroll 2
    for (int it = 0; it < 8; ++it) {
        int f = tid + it * 512;               // 4096 (row, 16B-unit) pairs
        int r = f >> 5, q = f & 31;
        const float* px = x + (size_t)(r0 + r) * DIM + q * 8;
        float4 v0 = *(const float4*)px;
        float4 v1 = *(const float4*)(px + 4);
        float fv[8] = {v0.x, v0.y, v0.z, v0.w, v1.x, v1.y, v1.z, v1.w};
        unsigned short hh[8], ll[8];
        #pragma unroll
        for (int j = 0; j < 8; ++j) {
            __nv_bfloat16 h = __float2bfloat16(fv[j]);
            __nv_bfloat16 l = __float2bfloat16(fv[j] - __bfloat162float(h));
            hh[j] = __bfloat16_as_ushort(h);
            ll[j] = __bfloat16_as_ushort(l);
        }
        uint4 uh = make_uint4(hh[0] | ((uint32_t)hh[1] << 16), hh[2] | ((uint32_t)hh[3] << 16),
                              hh[4] | ((uint32_t)hh[5] << 16), hh[6] | ((uint32_t)hh[7] << 16));
        uint4 ul = make_uint4(ll[0] | ((uint32_t)ll[1] << 16), ll[2] | ((uint32_t)ll[3] << 16),
                              ll[4] | ((uint32_t)ll[5] << 16), ll[6] | ((uint32_t)ll[7] << 16));
        uint32_t off = (r << 9) + (((q & 7) ^ (r & 7)) << 4) + ((q >> 3) << 7);
        *(uint4*)(sm_dyn + A_HI_OFF + off) = uh;
        *(uint4*)(sm_dyn + A_LO_OFF + off) = ul;
    }

    float acc[2][4][4];
    #pragma unroll
    for (int a = 0; a < 2; ++a)
        #pragma unroll
        for (int b = 0; b < 4; ++b)
            #pragma unroll
            for (int k = 0; k < 4; ++k) acc[a][b][k] = 0.f;

    float rb1[4], rb2[4]; int ri1[4], ri2[4];
    #pragma unroll
    for (int s = 0; s < 4; ++s) { rb1[s] = 3.4e38f; rb2[s] = 3.4e38f; ri1[s] = 0; ri2[s] = 0; }

    // ---- hoisted ldmatrix addressing ----
    const int r_in  = lane & 7;
    const int quad  = lane >> 3;
    const int lrow  = (quad & 1) * 8 + r_in;
    const int lq    = quad >> 1;          // 16B unit offset within 32B k-group
    const int rx    = lrow & 7;
    uint32_t aHi[2], aLo[2], bRowOff[2], sK[4];
    #pragma unroll
    for (int mf = 0; mf < 2; ++mf) {
        uint32_t ro = (uint32_t)(wm * 32 + mf * 16 + lrow) << 9;
        aHi[mf] = sbase + A_HI_OFF + ro;
        aLo[mf] = sbase + A_LO_OFF + ro;
    }
    #pragma unroll
    for (int g = 0; g < 2; ++g)
        bRowOff[g] = (uint32_t)(wn * 32 + g * 16 + lrow) << 7;
    #pragma unroll
    for (int ks = 0; ks < 4; ++ks)
        sK[ks] = (uint32_t)(((ks * 2 + lq) ^ rx) << 4);

    // ---- 3-stage pipeline prologue ----
    load_b_chunk(sbase, tid, 0, 0); CP_COMMIT();
    load_b_chunk(sbase, tid, 1, 1); CP_COMMIT();
    CP_WAIT1();
    __syncthreads();

    for (int c = 0; c < NCH; ++c) {
        const int stg = c - (c / 3) * 3;           // c % 3
        if (c + 2 < NCH) load_b_chunk(sbase, tid, c + 2, (c + 2) - ((c + 2) / 3) * 3);
        CP_COMMIT();

        const uint32_t bHiB = sbase + B_OFF + stg * BSTG;
        const uint32_t bLoB = bHiB + 16384;
        const uint32_t kcOff = (uint32_t)(c & 3) << 7;   // A unit advance per K-chunk

        #pragma unroll
        for (int ks = 0; ks < 4; ++ks) {
            uint32_t ah[2][4], al[2][4];
            #pragma unroll
            for (int mf = 0; mf < 2; ++mf) {
                LDSM4(ah[mf][0], ah[mf][1], ah[mf][2], ah[mf][3], aHi[mf] + kcOff + sK[ks]);
                LDSM4(al[mf][0], al[mf][1], al[mf][2], al[mf][3], aLo[mf] + kcOff + sK[ks]);
            }
            uint32_t bh[4][2], bl[4][2];
            #pragma unroll
            for (int g = 0; g < 2; ++g) {
                uint32_t t0, t1, t2, t3;
                LDSM4(t0, t1, t2, t3, bHiB + bRowOff[g] + sK[ks]);
                bh[g * 2 + 0][0] = t0; bh[g * 2 + 0][1] = t2;
                bh[g * 2 + 1][0] = t1; bh[g * 2 + 1][1] = t3;
                LDSM4(t0, t1, t2, t3, bLoB + bRowOff[g] + sK[ks]);
                bl[g * 2 + 0][0] = t0; bl[g * 2 + 0][1] = t2;
                bl[g * 2 + 1][0] = t1; bl[g * 2 + 1][1] = t3;
            }
            #pragma unroll
            for (int mf = 0; mf < 2; ++mf)
                #pragma unroll
                for (int nf = 0; nf < 4; ++nf) {
                    MMA16816(acc[mf][nf], ah[mf], bh[nf][0], bh[nf][1]);
                    MMA16816(acc[mf][nf], ah[mf], bl[nf][0], bl[nf][1]);
                    MMA16816(acc[mf][nf], al[mf], bh[nf][0], bh[nf][1]);
                }
        }

        if ((c & 3) == 3) {     // end of an N-tile: fold scores into argmin trackers
            const int nt = c >> 2;
            const int cbase = nt * NT + wn * 32 + (lane & 3) * 2;
            #pragma unroll
            for (int nf = 0; nf < 4; ++nf) {
                float2 en2 = __ldg((const float2*)(g_enorm + cbase + nf * 8));
                #pragma unroll
                for (int b = 0; b < 2; ++b) {
                    const float en  = b ? en2.y : en2.x;
                    const int  code = cbase + nf * 8 + b;
                    #pragma unroll
                    for (int mf = 0; mf < 2; ++mf)
                        #pragma unroll
                        for (int hf = 0; hf < 2; ++hf) {
                            float sc = fmaf(-2.f, acc[mf][nf][hf * 2 + b], en);
                            int s = mf * 2 + hf;
                            if (sc < rb2[s]) {
                                if (sc < rb1[s]) { rb2[s] = rb1[s]; ri2[s] = ri1[s];
                                                   rb1[s] = sc;     ri1[s] = code; }
                                else             { rb2[s] = sc;     ri2[s] = code; }
                            }
                        }
                }
            }
            #pragma unroll
            for (int a = 0; a < 2; ++a)
                #pragma unroll
                for (int b = 0; b < 4; ++b)
                    #pragma unroll
                    for (int k = 0; k < 4; ++k) acc[a][b][k] = 0.f;
        }

        CP_WAIT1();
        __syncthreads();
    }

    // ---- reduce best-2 across the 4 lanes sharing each row (quad shfl) ----
    #pragma unroll
    for (int s = 0; s < 4; ++s) {
        #pragma unroll
        for (int off = 1; off <= 2; off <<= 1) {
            float ob1 = __shfl_xor_sync(0xffffffffu, rb1[s], off);
            float ob2 = __shfl_xor_sync(0xffffffffu, rb2[s], off);
            int   oi1 = __shfl_xor_sync(0xffffffffu, ri1[s], off);
            int   oi2 = __shfl_xor_sync(0xffffffffu, ri2[s], off);
            if (ob1 < rb1[s] || (ob1 == rb1[s] && oi1 < ri1[s])) {
                float tb = rb1[s]; int ti = ri1[s];
                rb1[s] = ob1; ri1[s] = oi1; ob1 = tb; oi1 = ti;
            }
            if (ob1 < rb2[s]) { rb2[s] = ob1; ri2[s] = oi1; }
            if (ob2 < rb2[s]) { rb2[s] = ob2; ri2[s] = oi2; }
        }
    }
    __syncthreads();                     // done with B smem -> reuse as scratch
    if ((lane & 3) == 0) {
        #pragma unroll
        for (int s = 0; s < 4; ++s) {
            int mf = s >> 1, hf = s & 1;
            int row = wm * 32 + mf * 16 + (lane >> 2) + hf * 8;
            float4 v;
            v.x = rb1[s]; v.y = rb2[s];
            v.z = __int_as_float(ri1[s]); v.w = __int_as_float(ri2[s]);
            *(float4*)(sm_dyn + B_OFF + (wn * 128 + row) * 16) = v;
        }
    }
    __syncthreads();
    if (tid < 128) {
        float4 v = *(float4*)(sm_dyn + B_OFF + tid * 16);
        float b1 = v.x, b2 = v.y;
        int i1 = __float_as_int(v.z), i2 = __float_as_int(v.w);
        #pragma unroll
        for (int w = 1; w < 4; ++w) {
            float4 u = *(float4*)(sm_dyn + B_OFF + (w * 128 + tid) * 16);
            float ob1 = u.x, ob2 = u.y;
            int oi1 = __float_as_int(u.z), oi2 = __float_as_int(u.w);
            if (ob1 < b1 || (ob1 == b1 && oi1 < i1)) {
                float tb = b1; int ti = i1;
                b1 = ob1; i1 = oi1; ob1 = tb; oi1 = ti;
            }
            if (ob1 < b2) { b2 = ob1; i2 = oi1; }
            if (ob2 < b2) { b2 = ob2; i2 = oi2; }
        }
        int row = r0 + tid;
        g_ind[row] = i1; g_b1[row] = b1; g_b2[row] = b2; g_i2[row] = i2;
    }
}

// ======================= exact rescue for near-ties =======================
__global__ void vq_fixup_kernel(const float* __restrict__ x) {
    const int warp = threadIdx.x >> 5, lane = threadIdx.x & 31;
    const int row = blockIdx.x * 8 + warp;
    float b1 = g_b1[row], b2 = g_b2[row];
    if (b2 - b1 >= 0.01f) return;
    int i1 = g_ind[row], i2 = g_i2[row];
    const float* xr = x + (size_t)row * DIM;
    const float* e1 = g_embT + (size_t)i1 * DIM;
    const float* e2 = g_embT + (size_t)i2 * DIM;
    float d1 = 0.f, d2 = 0.f;
    #pragma unroll
    for (int t = lane; t < DIM; t += 32) {
        float xv = xr[t];
        d1 = fmaf(xv, e1[t], d1);
        d2 = fmaf(xv, e2[t], d2);
    }
    #pragma unroll
    for (int o = 16; o > 0; o >>= 1) {
        d1 += __shfl_xor_sync(0xffffffffu, d1, o);
        d2 += __shfl_xor_sync(0xffffffffu, d2, o);
    }
    if (lane == 0) {
        float s1 = g_enorm[i1] - 2.f * d1;
        float s2 = g_enorm[i2] - 2.f * d2;
        g_ind[row] = (s2 < s1 || (s2 == s1 && i2 < i1)) ? i2 : i1;
    }
}

// ======================= gather + loss =======================
__global__ void vq_gather_kernel(const float* __restrict__ x,
                                 float* __restrict__ outQ,
                                 float* __restrict__ outInd) {
    const int warp = threadIdx.x >> 5, lane = threadIdx.x & 31;
    const int row  = blockIdx.x * 8 + warp;
    const int j = g_ind[row];
    const float* e  = g_embT + (size_t)j * DIM;
    const float* xr = x + (size_t)row * DIM;
    float*       qo = outQ + (size_t)row * DIM;
    float s = 0.f;
    #pragma unroll
    for (int p = 0; p < 2; ++p) {
        float4 ev = *(const float4*)(e  + p * 128 + lane * 4);
        float4 xv = *(const float4*)(xr + p * 128 + lane * 4);
        float dx = ev.x - xv.x, dy = ev.y - xv.y, dz = ev.z - xv.z, dw = ev.w - xv.w;
        s += dx * dx + dy * dy + dz * dz + dw * dw;
        *(float4*)(qo + p * 128 + lane * 4) = ev;
    }
    #pragma unroll
    for (int o = 16; o > 0; o >>= 1) s += __shfl_xor_sync(0xffffffffu, s, o);
    __shared__ double bsum[8];
    if (lane == 0) { bsum[warp] = (double)s; outInd[row] = (float)j; }
    __syncthreads();
    if (threadIdx.x == 0) {
        double t = 0.0;
        #pragma unroll
        for (int w = 0; w < 8; ++w) t += bsum[w];
        atomicAdd(&g_diff_acc, t);
    }
}

__global__ void vq_finalize_kernel(float* __restrict__ outDiff) {
    if (threadIdx.x == 0)
        outDiff[0] = (float)(g_diff_acc * 1.25 / (double)QELEMS);
}

// ======================= launch =======================
extern "C" void kernel_launch(void* const* d_in, const int* in_sizes, int n_in,
                              void* d_out, int out_size) {
    const float* x     = (const float*)d_in[0];
    const float* embed = (const float*)d_in[1];
    float* out     = (float*)d_out;
    float* outQ    = out;
    float* outDiff = out + QELEMS;
    float* outInd  = out + QELEMS + 1;

    cudaFuncSetAttribute(vq_mma_kernel, cudaFuncAttributeMaxDynamicSharedMemorySize, SMEM_BYTES);

    vq_zero_kernel<<<1, 32>>>();
    vq_enorm_kernel<<<NCODES / 256, 256>>>(embed);
    vq_transpose_kernel<<<dim3(NCODES / 32, DIM / 32), dim3(32, 8)>>>(embed);
    vq_mma_kernel<<<N_ROWS / MTILE, 512, SMEM_BYTES>>>(x);
    vq_fixup_kernel<<<N_ROWS / 8, 256>>>(x);
    vq_gather_kernel<<<N_ROWS / 8, 256>>>(x, outQ, outInd);
    vq_finalize_kernel<<<1, 32>>>(outDiff);
}